// round 1
// baseline (speedup 1.0000x reference)
#include <cuda_runtime.h>
#include <math.h>

#define NB   4
#define LSEQ 2054
#define EE   512
#define HID  640
#define NHh  10
#define NC   527
#define MH   20      // 2 cls rows * NH heads
#define NCH  37      // n-chunks for weighted-feat kernel (grid = 37*4 = 148)
#define CHUNK 56     // ceil(2054/37)

typedef unsigned long long u64;

// ---------------- device scratch (no allocations allowed) ----------------
__device__ float g_pe[LSEQ*EE];          // positional encoding table
__device__ float g_k[NB*2*HID];          // k vectors for rows m=0,1029
__device__ float g_kq[NB*MH*EE];         // Wq_h^T k  per (b, m, h)
__device__ float g_cb[NB*MH];            // k . bq_h
__device__ float g_sc[NB*MH*LSEQ];       // scores -> exp(scores - max)
__device__ float g_den[NB*MH];           // softmax denominators
__device__ float g_wfp[NCH*NB*MH*EE];    // partial weighted feats
__device__ float g_wf[NB*MH*EE];         // reduced + normalized weighted feats
__device__ float g_cls[NB*2*HID];        // layernormed cls vectors

// ---------------- packed f32x2 helpers (Blackwell FFMA2 path) ----------------
__device__ __forceinline__ u64 pk2(float x, float y){
  u64 r; asm("mov.b64 %0,{%1,%2};" : "=l"(r) : "f"(x), "f"(y)); return r;
}
__device__ __forceinline__ float2 upk2(u64 v){
  float2 r; asm("mov.b64 {%0,%1},%2;" : "=f"(r.x), "=f"(r.y) : "l"(v)); return r;
}
__device__ __forceinline__ void fma2(u64 &d, u64 a, u64 b){
  asm("fma.rn.f32x2 %0,%1,%2,%0;" : "+l"(d) : "l"(a), "l"(b));
}
__device__ __forceinline__ u64 add2(u64 a, u64 b){
  u64 r; asm("add.rn.f32x2 %0,%1,%2;" : "=l"(r) : "l"(a), "l"(b)); return r;
}

// ---------------- token row resolver ----------------
// concat order: audio[0..1023], audio_tok[1024], btnk[1025..1028],
//               video[1029..2052], video_tok[2053]
__device__ __forceinline__ const float* row_src(int b, int n,
    const float* aud, const float* vid, const float* atok,
    const float* vtok, const float* btk){
  if (n < 1024)  return aud + ((size_t)b*1024 + n)*EE;
  if (n == 1024) return atok;
  if (n < 1029)  return btk + (size_t)(n-1025)*EE;
  if (n < 2053)  return vid + ((size_t)b*1024 + (n-1029))*EE;
  return vtok;
}

// ---------------- K0: positional encoding table ----------------
__global__ void k_pe(){
  int t = blockIdx.x*blockDim.x + threadIdx.x;   // grid 64 x 256 = 16384
  int e  = t & (EE-1);
  int n0 = t >> 9;                                // 0..31
  // div = exp(e_even * (-ln(10000)/512))
  float f = expf(-(float)(e & ~1) * (9.210340371976184f/512.0f));
  for (int n = n0; n < LSEQ; n += 32){
    float a = (float)n * f;
    g_pe[(size_t)n*EE + e] = (e & 1) ? cosf(a) : sinf(a);
  }
}

// ---------------- K1: k vectors for the 2 cls rows ----------------
__global__ void k_kvec(const float* __restrict__ aud, const float* __restrict__ vid,
                       const float* __restrict__ Wk, const float* __restrict__ bk){
  __shared__ float sf[EE];
  int bm = blockIdx.x, b = bm >> 1, m = bm & 1;
  int n  = m ? 1029 : 0;
  const float* src = m ? (vid + (size_t)b*1024*EE) : (aud + (size_t)b*1024*EE); // row 0
  int tid = threadIdx.x;                          // 640 threads
  if (tid < EE) sf[tid] = src[tid] + g_pe[(size_t)n*EE + tid];
  __syncthreads();
  float acc = bk[tid];
  #pragma unroll 8
  for (int e = 0; e < EE; e++) acc += sf[e]*Wk[(size_t)e*HID + tid];
  g_k[bm*HID + tid] = acc;
}

// ---------------- K2: kq[b,m,h,:] = Wq_h^T k, cb = k . bq_h ----------------
__global__ void k_kq(const float* __restrict__ Wq, const float* __restrict__ bq){
  __shared__ float kd[64];
  int blk = blockIdx.x;                           // b*MH + mh
  int b = blk / MH, mh = blk % MH, m = mh / NHh, h = mh % NHh;
  int tid = threadIdx.x;                          // 256
  if (tid < 64) kd[tid] = g_k[(b*2+m)*HID + h*64 + tid];
  __syncthreads();
  if (tid == 0){
    float s = 0.f;
    for (int d = 0; d < 64; d++) s += kd[d]*bq[h*64 + d];
    g_cb[blk] = s;
  }
  for (int e = tid; e < EE; e += 256){
    const float* w = Wq + (size_t)e*HID + h*64;
    float a = 0.f;
    #pragma unroll
    for (int d = 0; d < 64; d++) a += kd[d]*w[d];
    g_kq[(size_t)blk*EE + e] = a;
  }
}

// ---------------- K3: scores[b,mh,n] = (feats_n . kq + cb)/8 ----------------
__global__ void __launch_bounds__(256) k_scores(
    const float* __restrict__ aud, const float* __restrict__ vid,
    const float* __restrict__ atok, const float* __restrict__ vtok,
    const float* __restrict__ btk){
  __shared__ __align__(16) float s_kq[MH*EE];     // 40 KB
  __shared__ float s_cb[MH];
  int b = blockIdx.y;
  int tid = threadIdx.x;
  const float4* gk4 = (const float4*)(g_kq + (size_t)b*MH*EE);
  float4* sk4 = (float4*)s_kq;
  for (int i = tid; i < MH*EE/4; i += 256) sk4[i] = gk4[i];
  if (tid < MH) s_cb[tid] = g_cb[b*MH + tid];
  __syncthreads();
  int warp = tid >> 5, lane = tid & 31;
  for (int w4 = 0; w4 < 4; w4++){
    int n = blockIdx.x*32 + warp*4 + w4;
    if (n >= LSEQ) break;
    const float* src = row_src(b, n, aud, vid, atok, vtok, btk);
    const float* pe  = g_pe + (size_t)n*EE;
    u64 f2[8];
    #pragma unroll
    for (int i = 0; i < 4; i++){
      int off = lane*4 + 128*i;                   // coalesced float4 footprint
      f2[2*i]   = add2(*(const u64*)(src+off),   *(const u64*)(pe+off));
      f2[2*i+1] = add2(*(const u64*)(src+off+2), *(const u64*)(pe+off+2));
    }
    u64 acc[MH];
    #pragma unroll
    for (int q = 0; q < MH; q++) acc[q] = 0ull;
    #pragma unroll
    for (int j = 0; j < 8; j++){
      int pidx = lane*2 + (j & 1) + 64*(j >> 1);  // u64 index into the 512-wide row
      const u64* kp = (const u64*)s_kq + pidx;
      #pragma unroll
      for (int q = 0; q < MH; q++) fma2(acc[q], f2[j], kp[q*(EE/2)]);
    }
    #pragma unroll
    for (int q = 0; q < MH; q++){
      float2 v = upk2(acc[q]);
      float s = v.x + v.y;
      #pragma unroll
      for (int o = 16; o; o >>= 1) s += __shfl_xor_sync(0xffffffffu, s, o);
      if (lane == 0)
        g_sc[((size_t)(b*MH + q))*LSEQ + n] = (s + s_cb[q]) * 0.125f;
    }
  }
}

// ---------------- K4: softmax over n (store exp + denom) ----------------
__global__ void k_softmax(){
  int r = blockIdx.x;                             // b*MH + mh
  float* row = g_sc + (size_t)r*LSEQ;
  __shared__ float red[256];
  int tid = threadIdx.x;
  float m = -1e30f;
  for (int i = tid; i < LSEQ; i += 256) m = fmaxf(m, row[i]);
  red[tid] = m; __syncthreads();
  for (int s = 128; s; s >>= 1){ if (tid < s) red[tid] = fmaxf(red[tid], red[tid+s]); __syncthreads(); }
  float mx = red[0]; __syncthreads();
  float sum = 0.f;
  for (int i = tid; i < LSEQ; i += 256){
    float e = expf(row[i] - mx); row[i] = e; sum += e;
  }
  red[tid] = sum; __syncthreads();
  for (int s = 128; s; s >>= 1){ if (tid < s) red[tid] += red[tid+s]; __syncthreads(); }
  if (tid == 0) g_den[r] = red[0];
}

// ---------------- K5: partial weighted feats  wf = sum_n p_n * feats_n ----------------
__global__ void __launch_bounds__(128) k_wfeat(
    const float* __restrict__ aud, const float* __restrict__ vid,
    const float* __restrict__ atok, const float* __restrict__ vtok,
    const float* __restrict__ btk){
  __shared__ __align__(16) float s_p[CHUNK][MH];
  int c = blockIdx.x, b = blockIdx.y;
  int tid = threadIdx.x;                          // 128
  int n0 = c*CHUNK;
  int nend = LSEQ - n0; if (nend > CHUNK) nend = CHUNK;
  for (int i = tid; i < MH*CHUNK; i += 128){
    int mh = i / CHUNK, j = i % CHUNK;
    s_p[j][mh] = (j < nend) ? g_sc[((size_t)(b*MH+mh))*LSEQ + n0 + j] : 0.f;
  }
  __syncthreads();
  int e0 = tid*4;
  u64 accA[MH], accB[MH];
  #pragma unroll
  for (int q = 0; q < MH; q++){ accA[q] = 0ull; accB[q] = 0ull; }
  for (int jl = 0; jl < nend; jl++){
    int n = n0 + jl;
    const float* src = row_src(b, n, aud, vid, atok, vtok, btk);
    const float* pe  = g_pe + (size_t)n*EE + e0;
    u64 fa = add2(*(const u64*)(src + e0),     *(const u64*)(pe));
    u64 fb = add2(*(const u64*)(src + e0 + 2), *(const u64*)(pe + 2));
    const float4* pr = (const float4*)&s_p[jl][0];   // 5 x float4 = 20 probs
    #pragma unroll
    for (int g = 0; g < 5; g++){
      float4 p = pr[g];
      u64 p0 = pk2(p.x,p.x), p1 = pk2(p.y,p.y), p2_ = pk2(p.z,p.z), p3 = pk2(p.w,p.w);
      fma2(accA[4*g+0], p0, fa);  fma2(accB[4*g+0], p0, fb);
      fma2(accA[4*g+1], p1, fa);  fma2(accB[4*g+1], p1, fb);
      fma2(accA[4*g+2], p2_, fa); fma2(accB[4*g+2], p2_, fb);
      fma2(accA[4*g+3], p3, fa);  fma2(accB[4*g+3], p3, fb);
    }
  }
  float* dst = g_wfp + (((size_t)c*NB + b)*MH)*EE + e0;
  #pragma unroll
  for (int q = 0; q < MH; q++){
    float2 a = upk2(accA[q]); float2 bb = upk2(accB[q]);
    float4 o; o.x = a.x; o.y = a.y; o.z = bb.x; o.w = bb.y;
    *(float4*)(dst + (size_t)q*EE) = o;
  }
}

// ---------------- K5b: reduce chunk partials + normalize by softmax denom ----------------
__global__ void k_wreduce(){
  int r = blockIdx.x;                             // b*MH + mh
  int b = r / MH, mh = r % MH;
  int tid = threadIdx.x;                          // 128
  int e0 = tid*4;
  float4 s = make_float4(0.f,0.f,0.f,0.f);
  for (int c = 0; c < NCH; c++){
    float4 v = *(const float4*)(g_wfp + (((size_t)c*NB + b)*MH + mh)*EE + e0);
    s.x += v.x; s.y += v.y; s.z += v.z; s.w += v.w;
  }
  float inv = 1.f / g_den[r];
  s.x *= inv; s.y *= inv; s.z *= inv; s.w *= inv;
  *(float4*)(g_wf + (size_t)r*EE + e0) = s;
}

// ---------------- K6: Wv projection + LayerNorm -> cls vectors ----------------
__global__ void k_proj_ln(const float* __restrict__ Wv, const float* __restrict__ bv,
                          const float* __restrict__ lng, const float* __restrict__ lnb){
  __shared__ float s_wf[NHh*EE];                  // 20 KB
  __shared__ float red[HID];
  int bm = blockIdx.x;  int b = bm >> 1;  int m = bm & 1;
  int tid = threadIdx.x;                          // 640
  const float* src = g_wf + ((size_t)(b*MH + m*NHh))*EE;
  for (int i = tid; i < NHh*EE; i += HID) s_wf[i] = src[i];
  __syncthreads();
  int h = tid >> 6;
  const float* v = s_wf + h*EE;
  float acc = bv[tid];
  #pragma unroll 8
  for (int e = 0; e < EE; e++) acc += v[e]*Wv[(size_t)e*HID + tid];
  // mean
  red[tid] = acc; __syncthreads();
  if (tid < 128) red[tid] += red[tid+512]; __syncthreads();
  for (int s = 256; s; s >>= 1){ if (tid < s) red[tid] += red[tid+s]; __syncthreads(); }
  float mean = red[0] * (1.f/HID); __syncthreads();
  // variance
  float d = acc - mean;
  red[tid] = d*d; __syncthreads();
  if (tid < 128) red[tid] += red[tid+512]; __syncthreads();
  for (int s = 256; s; s >>= 1){ if (tid < s) red[tid] += red[tid+s]; __syncthreads(); }
  float var = red[0] * (1.f/HID);
  float y = d * rsqrtf(var + 1e-5f) * lng[tid] + lnb[tid];
  g_cls[(size_t)bm*HID + tid] = y;
}

// ---------------- K7: class projections + average ----------------
__global__ void k_cls(const float* __restrict__ Wap, const float* __restrict__ bap,
                      const float* __restrict__ Wvp, const float* __restrict__ bvp,
                      float* __restrict__ out){
  __shared__ float s_cls[8][HID];                 // 20 KB: all (b, m) cls vectors
  __shared__ float s_ra[8][32][4];
  __shared__ float s_rv[8][32][4];
  int tid = threadIdx.x;                          // 256
  for (int i = tid; i < 8*HID; i += 256) ((float*)s_cls)[i] = g_cls[i];
  __syncthreads();
  int cl = tid & 31, eg = tid >> 5;
  int c = blockIdx.x*32 + cl;
  float aA[4] = {0,0,0,0}, aV[4] = {0,0,0,0};
  if (c < NC){
    for (int e = eg; e < HID; e += 8){
      float wa = Wap[(size_t)e*NC + c];
      float wv = Wvp[(size_t)e*NC + c];
      #pragma unroll
      for (int b = 0; b < 4; b++){
        aA[b] += s_cls[b*2    ][e]*wa;
        aV[b] += s_cls[b*2 + 1][e]*wv;
      }
    }
  }
  #pragma unroll
  for (int b = 0; b < 4; b++){ s_ra[eg][cl][b] = aA[b]; s_rv[eg][cl][b] = aV[b]; }
  __syncthreads();
  if (tid < 128){
    int cl2 = tid & 31, b = tid >> 5;
    float a = 0.f, v = 0.f;
    #pragma unroll
    for (int g = 0; g < 8; g++){ a += s_ra[g][cl2][b]; v += s_rv[g][cl2][b]; }
    int c2 = blockIdx.x*32 + cl2;
    if (c2 < NC) out[(size_t)b*NC + c2] = 0.5f*((a + bap[c2]) + (v + bvp[c2]));
  }
}

// ---------------- launch ----------------
extern "C" void kernel_launch(void* const* d_in, const int* in_sizes, int n_in,
                              void* d_out, int out_size){
  const float* aud  = (const float*)d_in[0];
  const float* vid  = (const float*)d_in[1];
  const float* atok = (const float*)d_in[2];
  const float* vtok = (const float*)d_in[3];
  const float* btk  = (const float*)d_in[4];
  const float* Wk   = (const float*)d_in[5];
  const float* bk   = (const float*)d_in[6];
  const float* Wq   = (const float*)d_in[7];
  const float* bq   = (const float*)d_in[8];
  const float* Wv   = (const float*)d_in[9];
  const float* bv   = (const float*)d_in[10];
  const float* lng  = (const float*)d_in[11];
  const float* lnb  = (const float*)d_in[12];
  const float* Wap  = (const float*)d_in[13];
  const float* bap  = (const float*)d_in[14];
  const float* Wvp  = (const float*)d_in[15];
  const float* bvp  = (const float*)d_in[16];
  float* out = (float*)d_out;

  k_pe     <<<64, 256>>>();
  k_kvec   <<<8, 640>>>(aud, vid, Wk, bk);
  k_kq     <<<NB*MH, 256>>>(Wq, bq);
  k_scores <<<dim3(65, NB), 256>>>(aud, vid, atok, vtok, btk);
  k_softmax<<<NB*MH, 256>>>();
  k_wfeat  <<<dim3(NCH, NB), 128>>>(aud, vid, atok, vtok, btk);
  k_wreduce<<<NB*MH, 128>>>();
  k_proj_ln<<<8, 640>>>(Wv, bv, lng, lnb);
  k_cls    <<<17, 256>>>(Wap, bap, Wvp, bvp, out);
}

// round 2
// speedup vs baseline: 1.1664x; 1.1664x over previous
#include <cuda_runtime.h>
#include <math.h>

#define NB   4
#define LSEQ 2054
#define EE   512
#define HID  640
#define NHh  10
#define NC   527
#define MH   20      // 2 cls rows * 10 heads
#define NCH  37      // n-chunks for weighted-feat kernel (grid = 37*4 = 148)
#define CHUNK 56     // ceil(2054/37)
#define SNT  64      // k_scores n-tile per block
#define SNB  33      // ceil(2054/64)

typedef unsigned long long u64;

// ---------------- device scratch ----------------
__device__ float g_pe[LSEQ*EE];
__device__ float g_k[NB*2*HID];
__device__ u64   g_kq2[NB*256*MH];        // packed (e-pair, mh): (kq[2p],kq[2p+1])
__device__ float g_cb[NB*MH];
__device__ float g_sc[NB*MH*LSEQ];
__device__ float g_den[NB*MH];
__device__ float g_wfp[NCH*NB*MH*EE];
__device__ float g_wf[NB*MH*EE];
__device__ float g_cls[NB*2*HID];

// ---------------- packed f32x2 helpers ----------------
__device__ __forceinline__ u64 pk2(float x, float y){
  u64 r; asm("mov.b64 %0,{%1,%2};" : "=l"(r) : "f"(x), "f"(y)); return r;
}
__device__ __forceinline__ float2 upk2(u64 v){
  float2 r; asm("mov.b64 {%0,%1},%2;" : "=f"(r.x), "=f"(r.y) : "l"(v)); return r;
}
__device__ __forceinline__ void fma2(u64 &d, u64 a, u64 b){
  asm("fma.rn.f32x2 %0,%1,%2,%0;" : "+l"(d) : "l"(a), "l"(b));
}
__device__ __forceinline__ u64 add2(u64 a, u64 b){
  u64 r; asm("add.rn.f32x2 %0,%1,%2;" : "=l"(r) : "l"(a), "l"(b)); return r;
}

// ---------------- token row resolver ----------------
__device__ __forceinline__ const float* row_src(int b, int n,
    const float* aud, const float* vid, const float* atok,
    const float* vtok, const float* btk){
  if (n < 1024)  return aud + ((size_t)b*1024 + n)*EE;
  if (n == 1024) return atok;
  if (n < 1029)  return btk + (size_t)(n-1025)*EE;
  if (n < 2053)  return vid + ((size_t)b*1024 + (n-1029))*EE;
  return vtok;
}

// ---------------- K0: positional encoding (fast sincos + manual mod 2pi) ----
__global__ void k_pe(){
  int i = threadIdx.x;                      // 0..255 -> e-pair index
  float f = expf(-(float)(2*i) * (9.210340371976184f/512.0f));
  int n0 = blockIdx.x*4;
  #pragma unroll
  for (int k = 0; k < 4; k++){
    int n = n0 + k;
    if (n >= LSEQ) break;
    float a = (float)n * f;
    float r = rintf(a * 0.15915494309189535f);
    a = fmaf(r, -6.2831855f, a);
    a = fmaf(r, 1.7484556e-7f, a);
    float s, c; __sincosf(a, &s, &c);
    ((float2*)g_pe)[(size_t)n*(EE/2) + i] = make_float2(s, c);
  }
}

// ---------------- K1: k vectors for the 2 cls rows ----------------
__global__ void k_kvec(const float* __restrict__ aud, const float* __restrict__ vid,
                       const float* __restrict__ Wk, const float* __restrict__ bk){
  __shared__ float sf[EE];
  int bm = blockIdx.x, b = bm >> 1, m = bm & 1;
  int n  = m ? 1029 : 0;
  const float* src = m ? (vid + (size_t)b*1024*EE) : (aud + (size_t)b*1024*EE);
  int tid = threadIdx.x;                    // 640
  if (tid < EE) sf[tid] = src[tid] + g_pe[(size_t)n*EE + tid];
  __syncthreads();
  float a0=0.f, a1=0.f, a2=0.f, a3=0.f;
  const float* w = Wk + tid;
  #pragma unroll 4
  for (int e = 0; e < EE; e += 4){
    a0 = fmaf(sf[e+0], w[(size_t)(e+0)*HID], a0);
    a1 = fmaf(sf[e+1], w[(size_t)(e+1)*HID], a1);
    a2 = fmaf(sf[e+2], w[(size_t)(e+2)*HID], a2);
    a3 = fmaf(sf[e+3], w[(size_t)(e+3)*HID], a3);
  }
  g_k[bm*HID + tid] = bk[tid] + ((a0+a1)+(a2+a3));
}

// ---------------- K2: kq packed (e-pair, mh) + cb ----------------
__global__ void k_kq(const float* __restrict__ Wq, const float* __restrict__ bq){
  __shared__ float kd[64];
  int blk = blockIdx.x;                     // b*MH + mh
  int b = blk / MH, mh = blk % MH, m = mh / NHh, h = mh % NHh;
  int tid = threadIdx.x;                    // 256
  if (tid < 64) kd[tid] = g_k[(b*2+m)*HID + h*64 + tid];
  __syncthreads();
  if (tid == 0){
    float s = 0.f;
    for (int d = 0; d < 64; d++) s += kd[d]*bq[h*64 + d];
    g_cb[blk] = s;
  }
  int e0 = tid*2;
  float r0 = 0.f, r1 = 0.f;
  const float* w0 = Wq + (size_t)e0*HID + h*64;
  #pragma unroll 8
  for (int d = 0; d < 64; d++){
    r0 = fmaf(kd[d], w0[d],       r0);
    r1 = fmaf(kd[d], w0[HID + d], r1);
  }
  g_kq2[((size_t)b*256 + (e0>>1))*MH + mh] = pk2(r0, r1);
}

// ---------------- K3: scores — lane-owns-token, broadcast kq ----------------
// dyn smem: s_kq u64[256][20] (40960 B) | s_f float[64][130] (33280 B, reused
// as s_part float[4][64][20] in the epilogue)
__global__ void __launch_bounds__(256) k_scores(
    const float* __restrict__ aud, const float* __restrict__ vid,
    const float* __restrict__ atok, const float* __restrict__ vtok,
    const float* __restrict__ btk){
  extern __shared__ __align__(16) char dyn[];
  u64   (*s_kq)[MH]        = (u64(*)[MH])dyn;
  float (*s_f)[130]        = (float(*)[130])(dyn + 256*MH*8);
  float (*s_part)[SNT][MH] = (float(*)[SNT][MH])(dyn + 256*MH*8);
  __shared__ float s_cb[MH];

  int tid = threadIdx.x, b = blockIdx.y;
  {
    const u64* src = g_kq2 + (size_t)b*256*MH;
    u64* dst = (u64*)dyn;
    #pragma unroll 5
    for (int i = tid; i < 256*MH; i += 256) dst[i] = src[i];
  }
  if (tid < MH) s_cb[tid] = g_cb[b*MH + tid];

  int lane = tid & 31, warp = tid >> 5;
  int n_loc = tid & 63, esub = tid >> 6;
  int nbase = blockIdx.x*SNT;

  u64 acc[MH];
  #pragma unroll
  for (int q = 0; q < MH; q++) acc[q] = 0ull;

  for (int ec = 0; ec < 4; ec++){
    __syncthreads();
    // stage 64 rows x 128 e (chunk ec) into s_f[row][e], row stride 130
    #pragma unroll
    for (int jr = 0; jr < 8; jr++){
      int r  = warp*8 + jr;
      int nr = nbase + r; if (nr > LSEQ-1) nr = LSEQ-1;
      const float* src = row_src(b, nr, aud, vid, atok, vtok, btk) + ec*128;
      const float* pp  = g_pe + (size_t)nr*EE + ec*128;
      float4 x = *(const float4*)(src + lane*4);
      float4 y = *(const float4*)(pp  + lane*4);
      float* d = &s_f[r][lane*4];
      *(u64*)(d)   = pk2(x.x+y.x, x.y+y.y);
      *(u64*)(d+2) = pk2(x.z+y.z, x.w+y.w);
    }
    __syncthreads();
    // compute: thread owns token n_loc, e-pair quarter esub (16 pairs)
    #pragma unroll 4
    for (int ep = 0; ep < 16; ep++){
      int epc = esub*16 + ep;
      u64 f2 = *(const u64*)&s_f[n_loc][2*epc];
      const u64* kp = s_kq[ec*64 + epc];      // broadcast across warp
      #pragma unroll
      for (int q = 0; q < MH; q++) fma2(acc[q], f2, kp[q]);
    }
  }
  __syncthreads();
  #pragma unroll
  for (int q = 0; q < MH; q++){
    float2 v = upk2(acc[q]);
    s_part[esub][n_loc][q] = v.x + v.y;
  }
  __syncthreads();
  for (int i = tid; i < SNT*MH; i += 256){
    int nl = i / MH, q = i % MH;
    float s = s_part[0][nl][q] + s_part[1][nl][q]
            + s_part[2][nl][q] + s_part[3][nl][q];
    int n = nbase + nl;
    if (n < LSEQ)
      g_sc[((size_t)(b*MH + q))*LSEQ + n] = (s + s_cb[q]) * 0.125f;
  }
}

// ---------------- K4: softmax over n ----------------
__global__ void k_softmax(){
  int r = blockIdx.x;
  float* row = g_sc + (size_t)r*LSEQ;
  __shared__ float red[256];
  int tid = threadIdx.x;
  float m = -1e30f;
  for (int i = tid; i < LSEQ; i += 256) m = fmaxf(m, row[i]);
  red[tid] = m; __syncthreads();
  for (int s = 128; s; s >>= 1){ if (tid < s) red[tid] = fmaxf(red[tid], red[tid+s]); __syncthreads(); }
  float mx = red[0]; __syncthreads();
  float sum = 0.f;
  for (int i = tid; i < LSEQ; i += 256){
    float e = __expf(row[i] - mx); row[i] = e; sum += e;
  }
  red[tid] = sum; __syncthreads();
  for (int s = 128; s; s >>= 1){ if (tid < s) red[tid] += red[tid+s]; __syncthreads(); }
  if (tid == 0) g_den[r] = red[0];
}

// ---------------- K5: weighted feats (probs pre-packed u64) ----------------
__global__ void __launch_bounds__(256) k_wfeat(
    const float* __restrict__ aud, const float* __restrict__ vid,
    const float* __restrict__ atok, const float* __restrict__ vtok,
    const float* __restrict__ btk){
  __shared__ u64 s_p[CHUNK][MH];
  int c = blockIdx.x, b = blockIdx.y;
  int tid = threadIdx.x;                    // 256
  int n0 = c*CHUNK;
  int nend = LSEQ - n0; if (nend > CHUNK) nend = CHUNK;
  for (int i = tid; i < CHUNK*MH; i += 256){
    int j = i / MH, q = i % MH;
    float v = (j < nend) ? g_sc[((size_t)(b*MH+q))*LSEQ + n0 + j] : 0.f;
    s_p[j][q] = pk2(v, v);
  }
  __syncthreads();
  int e0 = tid*2;
  u64 acc[MH];
  #pragma unroll
  for (int q = 0; q < MH; q++) acc[q] = 0ull;
  #pragma unroll 2
  for (int jl = 0; jl < nend; jl++){
    int n = n0 + jl;
    const float* src = row_src(b, n, aud, vid, atok, vtok, btk);
    u64 f = add2(*(const u64*)(src + e0),
                 *(const u64*)(g_pe + (size_t)n*EE + e0));
    const u64* pp = s_p[jl];                // broadcast
    #pragma unroll
    for (int q = 0; q < MH; q++) fma2(acc[q], pp[q], f);
  }
  float* dst = g_wfp + ((size_t)(c*NB + b)*MH)*EE + e0;
  #pragma unroll
  for (int q = 0; q < MH; q++){
    float2 v = upk2(acc[q]);
    *(float2*)(dst + (size_t)q*EE) = v;
  }
}

// ---------------- K5b: reduce partials + softmax normalize ----------------
__global__ void k_wreduce(){
  int r = blockIdx.x;                       // b*MH + mh
  int b = r / MH, mh = r % MH;
  int tid = threadIdx.x;                    // 128
  int e0 = tid*4;
  float4 s = make_float4(0.f,0.f,0.f,0.f);
  #pragma unroll 4
  for (int c = 0; c < NCH; c++){
    float4 v = *(const float4*)(g_wfp + (((size_t)c*NB + b)*MH + mh)*EE + e0);
    s.x += v.x; s.y += v.y; s.z += v.z; s.w += v.w;
  }
  float inv = 1.f / g_den[r];
  s.x *= inv; s.y *= inv; s.z *= inv; s.w *= inv;
  *(float4*)(g_wf + (size_t)r*EE + e0) = s;
}

// ---------------- K6: Wv projection + LayerNorm ----------------
__global__ void k_proj_ln(const float* __restrict__ Wv, const float* __restrict__ bv,
                          const float* __restrict__ lng, const float* __restrict__ lnb){
  __shared__ float s_wf[NHh*EE];
  __shared__ float red[HID];
  int bm = blockIdx.x;  int b = bm >> 1;  int m = bm & 1;
  int tid = threadIdx.x;                    // 640
  const float* src = g_wf + ((size_t)(b*MH + m*NHh))*EE;
  for (int i = tid; i < NHh*EE; i += HID) s_wf[i] = src[i];
  __syncthreads();
  int h = tid >> 6;
  const float* v = s_wf + h*EE;
  const float* w = Wv + tid;
  float a0=0.f,a1=0.f,a2=0.f,a3=0.f;
  #pragma unroll 4
  for (int e = 0; e < EE; e += 4){
    a0 = fmaf(v[e+0], w[(size_t)(e+0)*HID], a0);
    a1 = fmaf(v[e+1], w[(size_t)(e+1)*HID], a1);
    a2 = fmaf(v[e+2], w[(size_t)(e+2)*HID], a2);
    a3 = fmaf(v[e+3], w[(size_t)(e+3)*HID], a3);
  }
  float acc = bv[tid] + ((a0+a1)+(a2+a3));
  red[tid] = acc; __syncthreads();
  if (tid < 128) red[tid] += red[tid+512]; __syncthreads();
  for (int s = 256; s; s >>= 1){ if (tid < s) red[tid] += red[tid+s]; __syncthreads(); }
  float mean = red[0] * (1.f/HID); __syncthreads();
  float d = acc - mean;
  red[tid] = d*d; __syncthreads();
  if (tid < 128) red[tid] += red[tid+512]; __syncthreads();
  for (int s = 256; s; s >>= 1){ if (tid < s) red[tid] += red[tid+s]; __syncthreads(); }
  float var = red[0] * (1.f/HID);
  float y = d * rsqrtf(var + 1e-5f) * lng[tid] + lnb[tid];
  g_cls[(size_t)bm*HID + tid] = y;
}

// ---------------- K7: class projections + average ----------------
__global__ void k_cls(const float* __restrict__ Wap, const float* __restrict__ bap,
                      const float* __restrict__ Wvp, const float* __restrict__ bvp,
                      float* __restrict__ out){
  __shared__ float s_cls[8][HID];
  __shared__ float s_ra[8][32][4];
  __shared__ float s_rv[8][32][4];
  int tid = threadIdx.x;                    // 256
  for (int i = tid; i < 8*HID; i += 256) ((float*)s_cls)[i] = g_cls[i];
  __syncthreads();
  int cl = tid & 31, eg = tid >> 5;
  int c = blockIdx.x*32 + cl;
  float aA[4] = {0,0,0,0}, aV[4] = {0,0,0,0};
  if (c < NC){
    #pragma unroll 4
    for (int e = eg; e < HID; e += 8){
      float wa = Wap[(size_t)e*NC + c];
      float wv = Wvp[(size_t)e*NC + c];
      #pragma unroll
      for (int b = 0; b < 4; b++){
        aA[b] += s_cls[b*2    ][e]*wa;
        aV[b] += s_cls[b*2 + 1][e]*wv;
      }
    }
  }
  #pragma unroll
  for (int b = 0; b < 4; b++){ s_ra[eg][cl][b] = aA[b]; s_rv[eg][cl][b] = aV[b]; }
  __syncthreads();
  if (tid < 128){
    int cl2 = tid & 31, b = tid >> 5;
    float a = 0.f, v = 0.f;
    #pragma unroll
    for (int g = 0; g < 8; g++){ a += s_ra[g][cl2][b]; v += s_rv[g][cl2][b]; }
    int c2 = blockIdx.x*32 + cl2;
    if (c2 < NC) out[(size_t)b*NC + c2] = 0.5f*((a + bap[c2]) + (v + bvp[c2]));
  }
}

// ---------------- launch ----------------
extern "C" void kernel_launch(void* const* d_in, const int* in_sizes, int n_in,
                              void* d_out, int out_size){
  const float* aud  = (const float*)d_in[0];
  const float* vid  = (const float*)d_in[1];
  const float* atok = (const float*)d_in[2];
  const float* vtok = (const float*)d_in[3];
  const float* btk  = (const float*)d_in[4];
  const float* Wk   = (const float*)d_in[5];
  const float* bk   = (const float*)d_in[6];
  const float* Wq   = (const float*)d_in[7];
  const float* bq   = (const float*)d_in[8];
  const float* Wv   = (const float*)d_in[9];
  const float* bv   = (const float*)d_in[10];
  const float* lng  = (const float*)d_in[11];
  const float* lnb  = (const float*)d_in[12];
  const float* Wap  = (const float*)d_in[13];
  const float* bap  = (const float*)d_in[14];
  const float* Wvp  = (const float*)d_in[15];
  const float* bvp  = (const float*)d_in[16];
  float* out = (float*)d_out;

  const int SC_SMEM = 256*MH*8 + 64*130*4;   // 74240 B
  cudaFuncSetAttribute(k_scores, cudaFuncAttributeMaxDynamicSharedMemorySize, SC_SMEM);

  k_pe     <<<(LSEQ+3)/4, 256>>>();
  k_kvec   <<<8, 640>>>(aud, vid, Wk, bk);
  k_kq     <<<NB*MH, 256>>>(Wq, bq);
  k_scores <<<dim3(SNB, NB), 256, SC_SMEM>>>(aud, vid, atok, vtok, btk);
  k_softmax<<<NB*MH, 256>>>();
  k_wfeat  <<<dim3(NCH, NB), 256>>>(aud, vid, atok, vtok, btk);
  k_wreduce<<<NB*MH, 128>>>();
  k_proj_ln<<<8, 640>>>(Wv, bv, lng, lnb);
  k_cls    <<<17, 256>>>(Wap, bap, Wvp, bvp, out);
}

// round 5
// speedup vs baseline: 1.2724x; 1.0909x over previous
#include <cuda_runtime.h>
#include <math.h>

#define NB    4
#define LSEQ  2054
#define LSEQT 2080     // padded featsT row (8320 B, 128B-aligned rows)
#define EE    512
#define HID   640
#define NHh   10
#define NC    527
#define MH    20       // 2 cls rows * 10 heads
#define NCH   37       // wfeat chunks (grid 37*4 = 148)
#define CHUNK 56
#define SNT   64       // scores n-tile
#define SNB   33       // ceil(2054/64)

typedef unsigned long long u64;

// ---------------- device scratch ----------------
__device__ __align__(128) float g_feats [NB*LSEQ*EE];    // feats+pe, n-major
__device__ __align__(128) float g_featsT[NB*EE*LSEQT];   // feats+pe, e-major
__device__ u64   g_kq2[NB*256*MH];
__device__ float g_cb[NB*MH];
__device__ float g_sc[NB*MH*LSEQ];
__device__ float g_den[NB*MH];
__device__ float g_wfp[NCH*NB*MH*EE];
__device__ float g_pp[4*8*HID];                          // (esplit, bm, col)
__device__ float g_cls[NB*2*HID];

// ---------------- packed f32x2 helpers ----------------
__device__ __forceinline__ u64 pk2(float x, float y){
  u64 r; asm("mov.b64 %0,{%1,%2};" : "=l"(r) : "f"(x), "f"(y)); return r;
}
__device__ __forceinline__ float2 upk2(u64 v){
  float2 r; asm("mov.b64 {%0,%1},%2;" : "=f"(r.x), "=f"(r.y) : "l"(v)); return r;
}
__device__ __forceinline__ void fma2(u64 &d, u64 a, u64 b){
  asm("fma.rn.f32x2 %0,%1,%2,%0;" : "+l"(d) : "l"(a), "l"(b));
}

__device__ __forceinline__ const float* row_src(int b, int n,
    const float* aud, const float* vid, const float* atok,
    const float* vtok, const float* btk){
  if (n < 1024)  return aud + ((size_t)b*1024 + n)*EE;
  if (n == 1024) return atok;
  if (n < 1029)  return btk + (size_t)(n-1025)*EE;
  if (n < 2053)  return vid + ((size_t)b*1024 + (n-1029))*EE;
  return vtok;
}

// ---------------- K0: feats+pe -> g_feats + g_featsT ----------------
__global__ void __launch_bounds__(256) k_feats(
    const float* __restrict__ aud, const float* __restrict__ vid,
    const float* __restrict__ atok, const float* __restrict__ vtok,
    const float* __restrict__ btk){
  __shared__ float s[32][33];
  int b = blockIdx.z, nbase = blockIdx.y*32, e0 = blockIdx.x*32;
  int tid = threadIdx.x;
  int lane = tid & 31, r8 = tid >> 5;
  int e = e0 + lane;
  float f = __expf(-(float)(e & ~1) * (9.210340371976184f/512.0f));
  bool odd = e & 1;
  #pragma unroll
  for (int rr = r8; rr < 32; rr += 8){
    int n = nbase + rr;
    float v = 0.f;
    if (n < LSEQ){
      const float* src = row_src(b, n, aud, vid, atok, vtok, btk);
      float a = (float)n * f;
      float q = rintf(a * 0.15915494309189535f);
      a = fmaf(q, -6.2831855f, a);
      a = fmaf(q, 1.7484556e-7f, a);
      float sn, cs; __sincosf(a, &sn, &cs);
      v = src[e] + (odd ? cs : sn);
      g_feats[((size_t)b*LSEQ + n)*EE + e] = v;
    }
    s[rr][lane] = v;
  }
  __syncthreads();
  int n = nbase + lane;
  if (n < LSEQ){
    #pragma unroll
    for (int ee = r8; ee < 32; ee += 8)
      g_featsT[((size_t)b*EE + e0 + ee)*LSEQT + n] = s[lane][ee];
  }
}

// ---------------- K1: k-slice + kq (fused, 80 blocks) ----------------
__global__ void __launch_bounds__(256) k_kq(
    const float* __restrict__ Wk, const float* __restrict__ bk,
    const float* __restrict__ Wq, const float* __restrict__ bq){
  __shared__ float sf[EE];
  __shared__ float spart[4][64];
  __shared__ float kk[64];
  int blk = blockIdx.x;
  int b = blk / MH, mh = blk % MH, m = mh / NHh, h = mh % NHh;
  int nrow = m ? 1029 : 0;
  int tid = threadIdx.x;
  for (int i = tid; i < EE; i += 256)
    sf[i] = g_feats[((size_t)b*LSEQ + nrow)*EE + i];
  __syncthreads();
  {
    int col = tid & 63, eg = tid >> 6;
    const float* w = Wk + h*64 + col;
    float p = 0.f;
    #pragma unroll 4
    for (int e = eg*128; e < eg*128 + 128; e++)
      p = fmaf(sf[e], w[(size_t)e*HID], p);
    spart[eg][col] = p;
  }
  __syncthreads();
  if (tid < 64)
    kk[tid] = bk[h*64 + tid] + ((spart[0][tid] + spart[1][tid]) +
                                (spart[2][tid] + spart[3][tid]));
  __syncthreads();
  if (tid == 0){
    float s = 0.f;
    for (int d = 0; d < 64; d++) s += kk[d]*bq[h*64 + d];
    g_cb[blk] = s;
  }
  int e0 = tid*2;
  const float4* w0 = (const float4*)(Wq + (size_t)e0*HID + h*64);
  const float4* w1 = (const float4*)(Wq + (size_t)(e0+1)*HID + h*64);
  float r0 = 0.f, r1 = 0.f;
  #pragma unroll
  for (int d4 = 0; d4 < 16; d4++){
    float4 a = w0[d4], c = w1[d4];
    float k0 = kk[4*d4], k1 = kk[4*d4+1], k2 = kk[4*d4+2], k3 = kk[4*d4+3];
    r0 = fmaf(k0,a.x, fmaf(k1,a.y, fmaf(k2,a.z, fmaf(k3,a.w, r0))));
    r1 = fmaf(k0,c.x, fmaf(k1,c.y, fmaf(k2,c.z, fmaf(k3,c.w, r1))));
  }
  g_kq2[((size_t)b*256 + tid)*MH + mh] = pk2(r0, r1);
}

// ---------------- K2: scores (lane-owns-token, featsT direct) ----------
// Dynamic smem: 40,960 B. s_kq (u64[256][MH]) lives there during the
// mainloop; after a sync the SAME buffer is reused as s_part
// (float[4][SNT][MH], 20,480 B). Static smem ~96 B. Total < 48 KB, so no
// cudaFuncSetAttribute is needed (the R3/R4 capture failures were launches
// exceeding the 48 KB opt-in-free smem limit).
__global__ void __launch_bounds__(256) k_scores(){
  extern __shared__ __align__(16) char dyn[];
  u64*  s_kq = (u64*)dyn;                          // [256][MH]
  float (*s_part)[SNT][MH] = (float(*)[SNT][MH])dyn;  // overlay after sync
  __shared__ float s_cb[MH];
  int tid = threadIdx.x, b = blockIdx.y;
  {
    const u64* src = g_kq2 + (size_t)b*256*MH;
    #pragma unroll 5
    for (int i = tid; i < 256*MH; i += 256) s_kq[i] = src[i];
  }
  if (tid < MH) s_cb[tid] = g_cb[b*MH + tid];
  __syncthreads();
  int slot = tid & 63, esub = tid >> 6;
  int nbase = blockIdx.x*SNT;
  int n = nbase + slot; if (n > LSEQ-1) n = LSEQ-1;
  const float* ft = g_featsT + ((size_t)b*EE + esub*128)*LSEQT + n;
  const u64* kqp = s_kq + (size_t)(esub*64)*MH;
  u64 acc[MH];
  #pragma unroll
  for (int q = 0; q < MH; q++) acc[q] = 0ull;
  #pragma unroll 8
  for (int ep = 0; ep < 64; ep++){
    float f0 = ft[(size_t)(2*ep  )*LSEQT];
    float f1 = ft[(size_t)(2*ep+1)*LSEQT];
    u64 f2 = pk2(f0, f1);
    const u64* kp = kqp + (size_t)ep*MH;
    #pragma unroll
    for (int q = 0; q < MH; q++) fma2(acc[q], f2, kp[q]);
  }
  __syncthreads();                 // all s_kq reads done before overlay write
  #pragma unroll
  for (int q = 0; q < MH; q++){
    float2 v = upk2(acc[q]);
    s_part[esub][slot][q] = v.x + v.y;
  }
  __syncthreads();
  for (int i = tid; i < SNT*MH; i += 256){
    int nl = i / MH, q = i % MH;
    float s = (s_part[0][nl][q] + s_part[1][nl][q]) +
              (s_part[2][nl][q] + s_part[3][nl][q]);
    int nn = nbase + nl;
    if (nn < LSEQ)
      g_sc[((size_t)(b*MH + q))*LSEQ + nn] = (s + s_cb[q]) * 0.125f;
  }
}

// ---------------- K3: softmax ----------------
__global__ void k_softmax(){
  int r = blockIdx.x;
  float* row = g_sc + (size_t)r*LSEQ;
  __shared__ float red[256];
  int tid = threadIdx.x;
  float m = -1e30f;
  for (int i = tid; i < LSEQ; i += 256) m = fmaxf(m, row[i]);
  red[tid] = m; __syncthreads();
  for (int s = 128; s; s >>= 1){ if (tid < s) red[tid] = fmaxf(red[tid], red[tid+s]); __syncthreads(); }
  float mx = red[0]; __syncthreads();
  float sum = 0.f;
  for (int i = tid; i < LSEQ; i += 256){
    float e = __expf(row[i] - mx); row[i] = e; sum += e;
  }
  red[tid] = sum; __syncthreads();
  for (int s = 128; s; s >>= 1){ if (tid < s) red[tid] += red[tid+s]; __syncthreads(); }
  if (tid == 0) g_den[r] = red[0];
}

// ---------------- K4: weighted feats partials ----------------
__global__ void __launch_bounds__(256) k_wfeat(){
  __shared__ u64 s_p[CHUNK][MH];
  int c = blockIdx.x, b = blockIdx.y;
  int tid = threadIdx.x;
  int n0 = c*CHUNK;
  int nend = LSEQ - n0; if (nend > CHUNK) nend = CHUNK;
  for (int i = tid; i < CHUNK*MH; i += 256){
    int j = i / MH, q = i % MH;
    float v = (j < nend) ? g_sc[((size_t)(b*MH + q))*LSEQ + n0 + j] : 0.f;
    s_p[j][q] = pk2(v, v);
  }
  __syncthreads();
  const float* fb = g_feats + ((size_t)b*LSEQ + n0)*EE + tid*2;
  u64 acc[MH];
  #pragma unroll
  for (int q = 0; q < MH; q++) acc[q] = 0ull;
  #pragma unroll 2
  for (int jl = 0; jl < nend; jl++){
    u64 f = *(const u64*)(fb + (size_t)jl*EE);
    const u64* pp = s_p[jl];
    #pragma unroll
    for (int q = 0; q < MH; q++) fma2(acc[q], pp[q], f);
  }
  float* dst = g_wfp + ((size_t)(c*NB + b)*MH)*EE + tid*2;
  #pragma unroll
  for (int q = 0; q < MH; q++){
    float2 v = upk2(acc[q]);
    *(float2*)(dst + (size_t)q*EE) = v;
  }
}

// ---------------- K5: Wv projection partials (40 blocks) ----------------
__global__ void __launch_bounds__(256) k_projpart(const float* __restrict__ Wv){
  __shared__ float4 s_wf4[8][32];                 // [bm][128e as float4]
  int h = blockIdx.x, es = blockIdx.y;
  int tid = threadIdx.x;
  {
    int bm = tid >> 5, j = tid & 31;
    int b = bm >> 1, m = bm & 1;
    int mh = m*NHh + h;
    float4 s = make_float4(0.f,0.f,0.f,0.f);
    #pragma unroll 4
    for (int c = 0; c < NCH; c++){
      float4 v = ((const float4*)(g_wfp + (((size_t)c*NB + b)*MH + mh)*EE + es*128))[j];
      s.x += v.x; s.y += v.y; s.z += v.z; s.w += v.w;
    }
    float inv = 1.f / g_den[b*MH + mh];
    s.x *= inv; s.y *= inv; s.z *= inv; s.w *= inv;
    s_wf4[bm][j] = s;
  }
  __syncthreads();
  const float* s_wf = (const float*)s_wf4;        // [bm][128]
  int col = tid & 63, bmg = tid >> 6;
  const float* wv = Wv + (size_t)(es*128)*HID + h*64 + col;
  float a0 = 0.f, a1 = 0.f;
  #pragma unroll 4
  for (int e = 0; e < 128; e++){
    float w = wv[(size_t)e*HID];
    a0 = fmaf(s_wf[ bmg    *128 + e], w, a0);
    a1 = fmaf(s_wf[(bmg+4)*128 + e], w, a1);
  }
  g_pp[((size_t)es*8 + bmg  )*HID + h*64 + col] = a0;
  g_pp[((size_t)es*8 + bmg+4)*HID + h*64 + col] = a1;
}

// ---------------- K6: combine + LayerNorm ----------------
__global__ void k_ln(const float* __restrict__ bv,
                     const float* __restrict__ lng, const float* __restrict__ lnb){
  __shared__ float red[HID];
  int bm = blockIdx.x, tid = threadIdx.x;         // 640
  float acc = bv[tid];
  #pragma unroll
  for (int es = 0; es < 4; es++) acc += g_pp[((size_t)es*8 + bm)*HID + tid];
  red[tid] = acc; __syncthreads();
  if (tid < 128) red[tid] += red[tid+512]; __syncthreads();
  for (int s = 256; s; s >>= 1){ if (tid < s) red[tid] += red[tid+s]; __syncthreads(); }
  float mean = red[0] * (1.f/HID); __syncthreads();
  float d = acc - mean;
  red[tid] = d*d; __syncthreads();
  if (tid < 128) red[tid] += red[tid+512]; __syncthreads();
  for (int s = 256; s; s >>= 1){ if (tid < s) red[tid] += red[tid+s]; __syncthreads(); }
  float var = red[0] * (1.f/HID);
  g_cls[(size_t)bm*HID + tid] = d * rsqrtf(var + 1e-5f) * lng[tid] + lnb[tid];
}

// ---------------- K7: class projections (33 blocks) ----------------
__global__ void __launch_bounds__(256) k_cls(
    const float* __restrict__ Wap, const float* __restrict__ bap,
    const float* __restrict__ Wvp, const float* __restrict__ bvp,
    float* __restrict__ out){
  __shared__ float s_cls[8][HID];
  __shared__ float s_ra[16][16][4];
  __shared__ float s_rv[16][16][4];
  int tid = threadIdx.x;
  for (int i = tid; i < 8*HID; i += 256) ((float*)s_cls)[i] = g_cls[i];
  __syncthreads();
  int cl = tid & 15, eg = tid >> 4;
  int c = blockIdx.x*16 + cl;
  float aA[4] = {0,0,0,0}, aV[4] = {0,0,0,0};
  if (c < NC){
    #pragma unroll 4
    for (int e = eg*40; e < eg*40 + 40; e++){
      float wa = Wap[(size_t)e*NC + c];
      float wv = Wvp[(size_t)e*NC + c];
      #pragma unroll
      for (int b = 0; b < 4; b++){
        aA[b] = fmaf(s_cls[b*2  ][e], wa, aA[b]);
        aV[b] = fmaf(s_cls[b*2+1][e], wv, aV[b]);
      }
    }
  }
  #pragma unroll
  for (int b = 0; b < 4; b++){ s_ra[eg][cl][b] = aA[b]; s_rv[eg][cl][b] = aV[b]; }
  __syncthreads();
  if (tid < 64){
    int cl2 = tid & 15, b = tid >> 4;
    float a = 0.f, v = 0.f;
    #pragma unroll
    for (int g = 0; g < 16; g++){ a += s_ra[g][cl2][b]; v += s_rv[g][cl2][b]; }
    int c2 = blockIdx.x*16 + cl2;
    if (c2 < NC) out[(size_t)b*NC + c2] = 0.5f*((a + bap[c2]) + (v + bvp[c2]));
  }
}

// ---------------- launch (plain stream launches; graph-capturable) --------
extern "C" void kernel_launch(void* const* d_in, const int* in_sizes, int n_in,
                              void* d_out, int out_size){
  const float* aud  = (const float*)d_in[0];
  const float* vid  = (const float*)d_in[1];
  const float* atok = (const float*)d_in[2];
  const float* vtok = (const float*)d_in[3];
  const float* btk  = (const float*)d_in[4];
  const float* Wk   = (const float*)d_in[5];
  const float* bk   = (const float*)d_in[6];
  const float* Wq   = (const float*)d_in[7];
  const float* bq   = (const float*)d_in[8];
  const float* Wv   = (const float*)d_in[9];
  const float* bv   = (const float*)d_in[10];
  const float* lng  = (const float*)d_in[11];
  const float* lnb  = (const float*)d_in[12];
  const float* Wap  = (const float*)d_in[13];
  const float* bap  = (const float*)d_in[14];
  const float* Wvp  = (const float*)d_in[15];
  const float* bvp  = (const float*)d_in[16];
  float* out = (float*)d_out;

  k_feats   <<<dim3(16,65,NB), 256>>>(aud, vid, atok, vtok, btk);
  k_kq      <<<NB*MH, 256>>>(Wk, bk, Wq, bq);
  k_scores  <<<dim3(SNB,NB), 256, 256*MH*8>>>();   // 40,960 B dynamic < 48 KB
  k_softmax <<<NB*MH, 256>>>();
  k_wfeat   <<<dim3(NCH,NB), 256>>>();
  k_projpart<<<dim3(NHh,4), 256>>>(Wv);
  k_ln      <<<8, HID>>>(bv, lng, lnb);
  k_cls     <<<33, 256>>>(Wap, bap, Wvp, bvp, out);
}